// round 16
// baseline (speedup 1.0000x reference)
#include <cuda_runtime.h>
#include <cuda_fp16.h>
#include <cstdint>

#define NB 16
#define CIN 64
#define HH 112
#define WW 112
#define COUT 128
#define HP 114                       // padded spatial (1-pixel halo)
#define HP2 (HP * HP)                // 12996
#define MPAD (NB * HP2)              // 207936 GEMM rows
#define KPT 192                      // K per tap (3 powers x 64 ci), halves
#define KTOT 1728                    // 9 taps * 192
#define KC 32                        // K halves per pipeline chunk (64B rows)
#define NCHUNK 54                    // 1728 / 32
#define STAGES 4
#define PITCH 40                     // halves per smem tile row (80B)
#define MT 128
#define NTILES ((MPAD + MT - 1) / MT)  // 1625
#define GRID_P 296                   // persistent CTAs = 148 SM x 2
#define A_TILE_H (MT * PITCH)        // halves per A (or B) tile
#define STAGE_H (2 * A_TILE_H)       // A + B = 10240 halves = 20480 B
#define SMEM_BYTES (STAGES * STAGE_H * 2)  // 81920

// scratch: padded fp16 powers matrix and fp16 weight matrix
__device__ __align__(128) __half g_P[(size_t)MPAD * KPT];   // [m][q*64+ci]
__device__ __align__(128) __half g_B[(size_t)COUT * KTOT];  // [co][tap*192+q*64+ci]

// ---------------------------------------------------------------------------
// PTX helpers (base PTX only — harness ptxas targets sm_103 family)
// ---------------------------------------------------------------------------
__device__ __forceinline__ uint32_t smem_u32(const void* p) {
    uint32_t a;
    asm("{ .reg .u64 t; cvta.to.shared.u64 t, %1; cvt.u32.u64 %0, t; }"
        : "=r"(a) : "l"(p));
    return a;
}

__device__ __forceinline__ void cp16(uint32_t dst, const void* src, uint32_t sz) {
    asm volatile("cp.async.cg.shared.global [%0], [%1], 16, %2;"
                 :: "r"(dst), "l"(src), "r"(sz) : "memory");
}

#define CP_COMMIT() asm volatile("cp.async.commit_group;" ::: "memory")
#define CP_WAIT3()  asm volatile("cp.async.wait_group 3;" ::: "memory")
#define CP_WAIT0()  asm volatile("cp.async.wait_group 0;" ::: "memory")

#define LDSM_X4(r0, r1, r2, r3, addr)                                         \
    asm volatile("ldmatrix.sync.aligned.m8n8.x4.shared.b16 {%0,%1,%2,%3}, [%4];" \
                 : "=r"(r0), "=r"(r1), "=r"(r2), "=r"(r3) : "r"(addr))

#define LDSM_X2(r0, r1, addr)                                                 \
    asm volatile("ldmatrix.sync.aligned.m8n8.x2.shared.b16 {%0,%1}, [%2];"    \
                 : "=r"(r0), "=r"(r1) : "r"(addr))

// fp16 inputs, fp32 accumulators
#define MMA_F16(c, a0, a1, a2, a3, b0, b1)                                    \
    asm volatile(                                                             \
        "mma.sync.aligned.m16n8k16.row.col.f32.f16.f16.f32 "                  \
        "{%0,%1,%2,%3}, {%4,%5,%6,%7}, {%8,%9}, {%0,%1,%2,%3};"               \
        : "+f"((c)[0]), "+f"((c)[1]), "+f"((c)[2]), "+f"((c)[3])              \
        : "r"(a0), "r"(a1), "r"(a2), "r"(a3), "r"(b0), "r"(b1))

// ---------------------------------------------------------------------------
// Kernel 1: fused bilinear shift + Maclaurin powers into padded fp16 matrix P.
// Phase 1: warp owns ci, lanes sweep wp (coalesced loads), sv[wp][ci].
// Phase 2: fixed per-thread (r = q,ci4), wp strides by 5 — zero div/mod.
// ---------------------------------------------------------------------------
__global__ void __launch_bounds__(256)
pbuild_kernel(const float* __restrict__ x, const float* __restrict__ shifts) {
    __shared__ float sv[HP][CIN + 1];   // pitch 65 (odd) -> conflict-free
    const int tid = threadIdx.x;
    const int lane = tid & 31;
    const int wid = tid >> 5;
    const int hp = blockIdx.x % HP;
    const int n = blockIdx.x / HP;
    const bool row_live = (hp >= 1) && (hp <= HH);

    for (int ci = wid; ci < CIN; ci += 8) {
        if (row_live) {
            const float sx = shifts[ci * 2 + 0] * 4.0f;
            const float sy = shifts[ci * 2 + 1] * 4.0f;
            const float iy = (float)(hp - 1) + sy;
            const float y0f = floorf(iy);
            const float wy = iy - y0f;
            const int y0 = (int)y0f;
            const bool vy0 = (y0 >= 0) && (y0 < HH);
            const bool vy1 = (y0 + 1 >= 0) && (y0 + 1 < HH);
            const float* xp0 =
                x + ((size_t)(n * CIN + ci) * HH + (vy0 ? y0 : 0)) * WW;
            const float* xp1 =
                x + ((size_t)(n * CIN + ci) * HH + (vy1 ? y0 + 1 : 0)) * WW;
            const float fy0 = vy0 ? (1.f - wy) : 0.f;
            const float fy1 = vy1 ? wy : 0.f;

            for (int wp = lane; wp < HP; wp += 32) {
                float v = 0.f;
                if (wp >= 1 && wp <= WW) {
                    const float jx = (float)(wp - 1) + sx;
                    const float x0f = floorf(jx);
                    const float wx = jx - x0f;
                    const int x0 = (int)x0f;
                    const bool vx0 = (x0 >= 0) && (x0 < WW);
                    const bool vx1 = (x0 + 1 >= 0) && (x0 + 1 < WW);
                    float v00 = vx0 ? xp0[x0] : 0.f;
                    float v01 = vx1 ? xp0[x0 + 1] : 0.f;
                    float v10 = vx0 ? xp1[x0] : 0.f;
                    float v11 = vx1 ? xp1[x0 + 1] : 0.f;
                    v = fy0 * ((1.f - wx) * v00 + wx * v01)
                      + fy1 * ((1.f - wx) * v10 + wx * v11);
                }
                sv[wp][ci] = v;
            }
        } else {
            for (int wp = lane; wp < HP; wp += 32) sv[wp][ci] = 0.f;
        }
    }
    __syncthreads();

    // phase 2: 240 active threads; r = (q, ci4) fixed per thread, wp stride 5
    if (tid < 240) {
        const int r = tid % 48;               // computed once
        const int q = r >> 4;                 // 0..2
        const int ci4 = (r & 15) * 4;
        __half* pb =
            g_P + (size_t)blockIdx.x * HP * KPT + q * 64 + ci4;
        for (int wp = tid / 48; wp < HP; wp += 5) {
            const float* svr = &sv[wp][ci4];
            __half h[4];
#pragma unroll
            for (int j = 0; j < 4; ++j) {
                const float v = svr[j];
                const float p = (q == 0) ? v : (q == 1 ? v * v : v * v * v);
                h[j] = __float2half_rn(p);
            }
            *(uint2*)(pb + (size_t)wp * KPT) = *(const uint2*)h;
        }
    }
}

// ---------------------------------------------------------------------------
// Kernel 2: weight matrix prep, K ordered (tap, q, ci), fp16
// ---------------------------------------------------------------------------
__global__ void bprep_kernel(const float* __restrict__ w) {
    int idx = blockIdx.x * blockDim.x + threadIdx.x;
    if (idx >= COUT * KTOT) return;
    int co = idx / KTOT;
    int kk = idx % KTOT;
    int tap = kk / KPT;
    int k2 = kk % KPT;
    int q = k2 >> 6;
    int ci = k2 & 63;
    int ky = tap / 3;
    int kx = tap % 3;
    g_B[idx] = __float2half_rn(
        w[(((size_t)co * (3 * CIN) + q * CIN + ci) * 3 + ky) * 3 + kx]);
}

// ---------------------------------------------------------------------------
// Kernel 3: PERSISTENT implicit-GEMM conv via mma.sync m16n8k16 fp16.
// 296 CTAs (2/SM) each process ~5.5 tiles of 128(M) x 128(N); per tile:
// K-chunks of 32 halves, 4-stage cp.async pipeline (wait_group 3),
// R11/R14-proven ordering. 8 warps as 2(M) x 4(N); warp tile 64x32.
// ---------------------------------------------------------------------------
__global__ void __launch_bounds__(256, 2)
gemm_kernel(const float* __restrict__ bias, float* __restrict__ out) {
    extern __shared__ __half smem[];
    const uint32_t sbase = smem_u32(smem);
    const int tid = threadIdx.x;
    const int lane = tid & 31;
    const int wid = tid >> 5;

    const int warpM = (wid >> 2) * 64;
    const int warpN = (wid & 3) * 32;

    // ldmatrix per-thread source coordinates (16x16 A tiles, 8x16 B tiles)
    const int aRow = ((lane >> 3) & 1) * 8 + (lane & 7);
    const int aKseg = (lane >> 4) * 8;
    const uint32_t aAddr0 =
        sbase + (uint32_t)(((warpM + aRow) * PITCH + aKseg) * 2);
    const int bRow = lane & 7;
    const int bKseg = ((lane >> 3) & 1) * 8;
    const uint32_t bAddr0 = sbase + (uint32_t)(A_TILE_H * 2) +
                            (uint32_t)(((warpN + bRow) * PITCH + bKseg) * 2);

    // cp.async coordinates: 4 adjacent lanes = one full 64B row (PROVEN law)
    const int r0 = tid >> 2, kc = tid & 3;   // row 0..63, 16B seg 0..3
    const int r1 = r0 + 64;

#pragma unroll 1
    for (int tile = blockIdx.x; tile < NTILES; tile += GRID_P) {
        const long long m0 = (long long)tile * MT;

        float acc[4][4][4];
#pragma unroll
        for (int i = 0; i < 4; ++i)
#pragma unroll
            for (int j = 0; j < 4; ++j)
#pragma unroll
                for (int k = 0; k < 4; ++k) acc[i][j][k] = 0.f;

        // -------- stage loader: one K=32 chunk (A 128x32h + B 128x32h) ----
        auto load_chunk = [&](int c, int s) {
            const int tap = c / 6;
            const int inner = (c % 6) * KC;
            const int toff = (tap / 3 - 1) * HP + (tap % 3 - 1);
            const uint32_t dA = sbase + (uint32_t)(s * STAGE_H * 2);
            const uint32_t dB = dA + (uint32_t)(A_TILE_H * 2);

            {
                long long grow = m0 + r0 + toff;
                bool ok = (grow >= 0) && (grow < (long long)MPAD);
                const __half* srcA =
                    g_P + (ok ? grow : 0) * KPT + inner + kc * 8;
                cp16(dA + (uint32_t)((r0 * PITCH + kc * 8) * 2), srcA,
                     ok ? 16u : 0u);
                cp16(dB + (uint32_t)((r0 * PITCH + kc * 8) * 2),
                     g_B + (size_t)r0 * KTOT + c * KC + kc * 8, 16u);
            }
            {
                long long grow = m0 + r1 + toff;
                bool ok = (grow >= 0) && (grow < (long long)MPAD);
                const __half* srcA =
                    g_P + (ok ? grow : 0) * KPT + inner + kc * 8;
                cp16(dA + (uint32_t)((r1 * PITCH + kc * 8) * 2), srcA,
                     ok ? 16u : 0u);
                cp16(dB + (uint32_t)((r1 * PITCH + kc * 8) * 2),
                     g_B + (size_t)r1 * KTOT + c * KC + kc * 8, 16u);
            }
            CP_COMMIT();
        };

        // prologue: stages 0..2
#pragma unroll
        for (int s = 0; s < STAGES - 1; ++s) load_chunk(s, s);

        // -------- main loop --------
#pragma unroll 1
        for (int c = 0; c < NCHUNK; ++c) {
            const int cpre = c + STAGES - 1;
            if (cpre < NCHUNK) load_chunk(cpre, cpre & (STAGES - 1));
            else CP_COMMIT();
            CP_WAIT3();
            __syncthreads();

            const uint32_t soff = (uint32_t)((c & (STAGES - 1)) * STAGE_H * 2);
            const uint32_t sa = aAddr0 + soff;
            const uint32_t sb = bAddr0 + soff;

#pragma unroll
            for (int ks = 0; ks < 2; ++ks) {
                const uint32_t koff = (uint32_t)(ks * 16 * 2);  // 16 halves
                uint32_t b0[4], b1[4];
#pragma unroll
                for (int nt = 0; nt < 4; ++nt)
                    LDSM_X2(b0[nt], b1[nt],
                            sb + (uint32_t)(nt * 8 * PITCH * 2) + koff);
#pragma unroll
                for (int mt = 0; mt < 4; ++mt) {
                    uint32_t a0, a1, a2, a3;
                    LDSM_X4(a0, a1, a2, a3,
                            sa + (uint32_t)(mt * 16 * PITCH * 2) + koff);
#pragma unroll
                    for (int nt = 0; nt < 4; ++nt)
                        MMA_F16(acc[mt][nt], a0, a1, a2, a3, b0[nt], b1[nt]);
                }
            }
            __syncthreads();
        }
        CP_WAIT0();   // drain the tail dummy groups before next tile reuse

        // -------- epilogue --------
#pragma unroll
        for (int mt = 0; mt < 4; ++mt) {
#pragma unroll
            for (int half = 0; half < 2; ++half) {
                long long m = m0 + warpM + mt * 16 + (lane >> 2) + half * 8;
                if (m >= (long long)MPAD) continue;
                int mi = (int)m;
                int nb = mi / HP2;
                int rem = mi % HP2;
                int hp = rem / HP;
                int wp = rem % HP;
                if (hp < 1 || hp > HH || wp < 1 || wp > WW) continue;
                float* op =
                    out + (((size_t)nb * COUT) * HH + (hp - 1)) * WW + (wp - 1);
#pragma unroll
                for (int nt = 0; nt < 4; ++nt) {
                    int co = warpN + nt * 8 + 2 * (lane & 3);
                    op[(size_t)co * (HH * WW)] =
                        acc[mt][nt][half * 2 + 0] + __ldg(bias + co);
                    op[(size_t)(co + 1) * (HH * WW)] =
                        acc[mt][nt][half * 2 + 1] + __ldg(bias + co + 1);
                }
            }
        }
        __syncthreads();  // all reads of this tile's smem done before refill
    }
}

// ---------------------------------------------------------------------------
extern "C" void kernel_launch(void* const* d_in, const int* in_sizes, int n_in,
                              void* d_out, int out_size) {
    const float* x = (const float*)d_in[0];
    const float* weights = (const float*)d_in[1];
    const float* bias = (const float*)d_in[2];
    const float* shifts = (const float*)d_in[3];
    float* out = (float*)d_out;

    pbuild_kernel<<<NB * HP, 256>>>(x, shifts);
    bprep_kernel<<<(COUT * KTOT + 255) / 256, 256>>>(weights);

    cudaFuncSetAttribute(gemm_kernel,
                         cudaFuncAttributeMaxDynamicSharedMemorySize,
                         SMEM_BYTES);
    gemm_kernel<<<GRID_P, 256, SMEM_BYTES>>>(bias, out);
}